// round 10
// baseline (speedup 1.0000x reference)
#include <cuda_runtime.h>

namespace {
constexpr int   Bb     = 256;
constexpr int   Nn     = 128;
constexpr int   Mm     = 192;
constexpr int   PA     = 129;   // smem pitch (odd -> conflict-free rows AND columns)
constexpr int   PH     = 129;
constexpr float RHO    = 0.1f;
constexpr float SIGMA  = 1e-6f;
constexpr float ALPHA  = 1.6f;
constexpr int   NITERS = 400;
constexpr int   NT     = 512;   // 16 warps -> 4 per SMSP
constexpr int   PPART  = 144;   // partial pitch (144%32==16 -> halves hit disjoint banks)

// shared memory layout (floats)
constexpr int OFF_A    = 0;                   // A pitched (dead after reg load;
                                              // start reused as P1 partials 16xPPART)
constexpr int OFF_H    = OFF_A + Mm * PA;     // H then H^{-1}
constexpr int OFF_Q    = OFF_H + Nn * PH;
constexpr int OFF_L    = OFF_Q + Nn;
constexpr int OFF_U    = OFF_L + Mm;
constexpr int OFF_X    = OFF_U + Mm;
constexpr int OFF_Z    = OFF_X + Nn;
constexpr int OFF_Y    = OFF_Z + Mm;
constexpr int OFF_W    = OFF_Y + Mm;
constexpr int OFF_RHS  = OFF_W + Mm;
constexpr int OFF_XT   = OFF_RHS + Nn;
constexpr int OFF_SNAP = OFF_XT + Nn;         // 256 floats: GJ row/col snapshots
constexpr int SMEM_FLOATS = OFF_SNAP + 256;
static_assert(16 * PPART <= Mm * PA, "P1 partials must fit in dead A region");
static_assert(SMEM_FLOATS * 4 <= 227 * 1024, "");
}

extern __shared__ float smem[];

__global__ __launch_bounds__(NT, 1)
void osqp_admm_kernel(const float* __restrict__ gP,
                      const float* __restrict__ gq,
                      const float* __restrict__ gA,
                      const float* __restrict__ gl,
                      const float* __restrict__ gu,
                      float* __restrict__ gout)
{
    const int b   = blockIdx.x;
    const int tid = threadIdx.x;
    const int ty  = tid >> 4;        // 0..31
    const int tx  = tid & 15;        // 0..15
    const int wrp = tid >> 5;        // 0..15

    float* sA    = smem + OFF_A;
    float* sH    = smem + OFF_H;
    float* sq    = smem + OFF_Q;
    float* sl    = smem + OFF_L;
    float* su    = smem + OFF_U;
    float* sx    = smem + OFF_X;
    float* sz    = smem + OFF_Z;
    float* sy    = smem + OFF_Y;
    float* sw    = smem + OFF_W;
    float* srhs  = smem + OFF_RHS;
    float* sxt   = smem + OFF_XT;
    float* snap  = smem + OFF_SNAP;
    float* spart = smem + OFF_A;     // P1 partials (16 x PPART), aliases dead A

    // ------------------------------------------------------------------
    // Phase 0: load A (pitched), H = P + sigma*I, vectors; init state
    // ------------------------------------------------------------------
    {
        const float* pA = gA + (size_t)b * Mm * Nn;
        for (int idx = tid; idx < Mm * Nn; idx += NT)
            sA[(idx >> 7) * PA + (idx & 127)] = pA[idx];

        const float* pP = gP + (size_t)b * Nn * Nn;
        for (int idx = tid; idx < Nn * Nn; idx += NT) {
            int i = idx >> 7, j = idx & 127;
            float v = pP[idx];
            if (i == j) v += SIGMA;
            sH[i * PH + j] = v;
        }
        for (int n = tid; n < Nn; n += NT) { sq[n] = gq[(size_t)b * Nn + n]; sx[n] = 0.f; }
        for (int m = tid; m < Mm; m += NT) {
            sl[m] = gl[(size_t)b * Mm + m];
            su[m] = gu[(size_t)b * Mm + m];
            sz[m] = 0.f; sy[m] = 0.f; sw[m] = 0.f;
        }
    }
    __syncthreads();

    // ------------------------------------------------------------------
    // Phase 1: H += rho * A^T A   (8x4 register tile, 16x32 thread grid)
    // ------------------------------------------------------------------
    {
        const int ty1 = tid >> 5;    // 0..15
        const int tx1 = tid & 31;    // 0..31
        const int i0  = ty1 * 8;
        float acc[8][4];
        #pragma unroll
        for (int r = 0; r < 8; r++)
            #pragma unroll
            for (int c = 0; c < 4; c++) acc[r][c] = 0.f;

        #pragma unroll 2
        for (int m = 0; m < Mm; m++) {
            const float* row = sA + m * PA;
            float av[8], bv[4];
            #pragma unroll
            for (int r = 0; r < 8; r++) av[r] = row[i0 + r];       // broadcast
            #pragma unroll
            for (int c = 0; c < 4; c++) bv[c] = row[tx1 + 32 * c]; // coalesced
            #pragma unroll
            for (int r = 0; r < 8; r++)
                #pragma unroll
                for (int c = 0; c < 4; c++)
                    acc[r][c] += av[r] * bv[c];
        }
        #pragma unroll
        for (int r = 0; r < 8; r++)
            #pragma unroll
            for (int c = 0; c < 4; c++)
                sH[(i0 + r) * PH + tx1 + 32 * c] += RHO * acc[r][c];
    }
    __syncthreads();

    // ------------------------------------------------------------------
    // Phase 2: in-place Gauss-Jordan inverse of H (SPD -> no pivoting)
    // ------------------------------------------------------------------
    {
        float* srk = snap;         // row-k snapshot (128)
        float* sck = snap + Nn;    // col-k snapshot (128)
        for (int k = 0; k < Nn; k++) {
            const float p = 1.0f / sH[k * PH + k];
            if (tid < Nn)            srk[tid] = sH[k * PH + tid];
            else if (tid < 2 * Nn)   sck[tid - Nn] = sH[(tid - Nn) * PH + k];
            __syncthreads();

            const int  j   = tid & 127;
            const int  i0  = (tid >> 7) * 32;
            const float rs = srk[j] * p;
            const bool jk  = (j == k);
            #pragma unroll 4
            for (int i = i0; i < i0 + 32; i++) {
                float hij = sH[i * PH + j];
                float f   = sck[i];
                float nv;
                if (i == k) nv = jk ? p : rs;
                else        nv = jk ? (-f * p) : fmaf(-f, rs, hij);
                sH[i * PH + j] = nv;
            }
            __syncthreads();
        }
    }
    // sH now holds M1 = H^{-1}

    // ------------------------------------------------------------------
    // Phase 2b: load A and M1 into registers.
    //   rA[k][j] = A[ty+32k][tx+16j]   (6 x 8 per thread)
    //   rM[k][j] = M1[ty+32k][tx+16j]  (4 x 8 per thread)
    // ------------------------------------------------------------------
    float rA[6][8];
    #pragma unroll
    for (int k = 0; k < 6; k++)
        #pragma unroll
        for (int j = 0; j < 8; j++)
            rA[k][j] = sA[(ty + 32 * k) * PA + (tx + 16 * j)];

    float rM[4][8];
    #pragma unroll
    for (int k = 0; k < 4; k++)
        #pragma unroll
        for (int j = 0; j < 8; j++)
            rM[k][j] = sH[(ty + 32 * k) * PH + (tx + 16 * j)];

    __syncthreads();   // all sA reads done before spart aliases it

    // ------------------------------------------------------------------
    // Phase 3: 400 ADMM iterations; matrices in registers, 16 warps.
    // ------------------------------------------------------------------
    for (int it = 0; it < NITERS; it++) {
        // ---- P1: partial A^T w over this thread's 6 m-rows, then merge
        //      the warp's two ty-halves with one full-width shfl ----
        {
            float p[8];
            #pragma unroll
            for (int j = 0; j < 8; j++) p[j] = 0.f;
            #pragma unroll
            for (int k = 0; k < 6; k++) {
                const float wk = sw[ty + 32 * k];
                #pragma unroll
                for (int j = 0; j < 8; j++)
                    p[j] = fmaf(rA[k][j], wk, p[j]);
            }
            #pragma unroll
            for (int j = 0; j < 8; j++)
                p[j] += __shfl_xor_sync(0xffffffffu, p[j], 16);  // merge ty pair
            if (ty == 2 * wrp) {   // lower half stores the merged row
                #pragma unroll
                for (int j = 0; j < 8; j++)
                    spart[wrp * PPART + tx + 16 * j] = p[j];
            }
        }
        __syncthreads();

        // ---- P2: combine rhs (threads 0..127, one column; 16 partials) ----
        if (tid < Nn) {
            float s0 = 0.f, s1 = 0.f, s2 = 0.f, s3 = 0.f;
            #pragma unroll
            for (int t = 0; t < 16; t += 4) {
                s0 += spart[(t + 0) * PPART + tid];
                s1 += spart[(t + 1) * PPART + tid];
                s2 += spart[(t + 2) * PPART + tid];
                s3 += spart[(t + 3) * PPART + tid];
            }
            srhs[tid] = fmaf(SIGMA, sx[tid], ((s0 + s1) + (s2 + s3)) - sq[tid]);
        }
        __syncthreads();

        // ---- P3: xt = M1 * rhs (16-wide butterfly) + x update ----
        {
            float t4[4];
            #pragma unroll
            for (int k = 0; k < 4; k++) t4[k] = 0.f;
            #pragma unroll
            for (int j = 0; j < 8; j++) {
                const float rj = srhs[tx + 16 * j];
                #pragma unroll
                for (int k = 0; k < 4; k++)
                    t4[k] = fmaf(rM[k][j], rj, t4[k]);
            }
            #pragma unroll
            for (int s = 8; s >= 1; s >>= 1)
                #pragma unroll
                for (int k = 0; k < 4; k++)
                    t4[k] += __shfl_xor_sync(0xffffffffu, t4[k], s, 16);
            // every lane holds all 4 sums; lanes 0..3 each write one element
            if (tx < 4) {
                const int   i  = ty + 32 * tx;
                const float v  = t4[tx];
                sxt[i] = v;
                sx[i]  = fmaf(ALPHA, v, (1.0f - ALPHA) * sx[i]);
            }
        }
        __syncthreads();

        // ---- P5: zt = A*xt (butterfly) fused with z/y/w update ----
        {
            float p6[6];
            #pragma unroll
            for (int k = 0; k < 6; k++) p6[k] = 0.f;
            #pragma unroll
            for (int j = 0; j < 8; j++) {
                const float xj = sxt[tx + 16 * j];
                #pragma unroll
                for (int k = 0; k < 6; k++)
                    p6[k] = fmaf(rA[k][j], xj, p6[k]);
            }
            #pragma unroll
            for (int s = 8; s >= 1; s >>= 1)
                #pragma unroll
                for (int k = 0; k < 6; k++)
                    p6[k] += __shfl_xor_sync(0xffffffffu, p6[k], s, 16);
            // lanes 0..5 each update one m in parallel
            if (tx < 6) {
                const int   m  = ty + 32 * tx;
                const float zc = fmaf(ALPHA, p6[tx], (1.0f - ALPHA) * sz[m]);
                const float yv = sy[m];
                const float v  = fmaf(yv, 1.0f / RHO, zc);
                const float zn = fminf(fmaxf(v, sl[m]), su[m]);
                const float yn = fmaf(RHO, zc - zn, yv);
                sz[m] = zn;
                sy[m] = yn;
                sw[m] = fmaf(RHO, zn, -yn);
            }
        }
        __syncthreads();
    }

    // ------------------------------------------------------------------
    // Output
    // ------------------------------------------------------------------
    for (int n = tid; n < Nn; n += NT)
        gout[(size_t)b * Nn + n] = sx[n];
}

extern "C" void kernel_launch(void* const* d_in, const int* in_sizes, int n_in,
                              void* d_out, int out_size)
{
    const float* P = (const float*)d_in[0];   // (256,128,128)
    const float* q = (const float*)d_in[1];   // (256,128)
    const float* A = (const float*)d_in[2];   // (256,192,128)
    const float* l = (const float*)d_in[3];   // (256,192)
    const float* u = (const float*)d_in[4];   // (256,192)
    float* out = (float*)d_out;               // (256,128)

    const int smem_bytes = SMEM_FLOATS * (int)sizeof(float);
    // Unconditional (no static guard). Not stream-ordered -> capture-legal; idempotent.
    cudaFuncSetAttribute(osqp_admm_kernel,
                         cudaFuncAttributeMaxDynamicSharedMemorySize,
                         smem_bytes);
    osqp_admm_kernel<<<Bb, NT, smem_bytes>>>(P, q, A, l, u, out);
}

// round 11
// speedup vs baseline: 1.8025x; 1.8025x over previous
#include <cuda_runtime.h>

namespace {
constexpr int   Bb     = 256;
constexpr int   Nn     = 128;
constexpr int   Mm     = 192;
constexpr int   PA     = 129;   // smem pitch (odd -> conflict-free rows AND columns)
constexpr int   PH     = 129;
constexpr float RHO    = 0.1f;
constexpr float SIGMA  = 1e-6f;
constexpr float ALPHA  = 1.6f;
constexpr int   NITERS = 400;
constexpr int   NT     = 512;   // 16 warps -> 4 per SMSP
constexpr int   PPART  = 144;   // partial pitch (144%32==16 -> halves hit disjoint banks)

// shared memory layout (floats)
constexpr int OFF_A    = 0;                   // A pitched (dead after reg load;
                                              // start reused as P1 partials 16xPPART)
constexpr int OFF_H    = OFF_A + Mm * PA;     // H then H^{-1}
constexpr int OFF_Q    = OFF_H + Nn * PH;
constexpr int OFF_L    = OFF_Q + Nn;
constexpr int OFF_U    = OFF_L + Mm;
constexpr int OFF_X    = OFF_U + Mm;
constexpr int OFF_Z    = OFF_X + Nn;
constexpr int OFF_Y    = OFF_Z + Mm;
constexpr int OFF_W    = OFF_Y + Mm;
constexpr int OFF_RHS  = OFF_W + Mm;
constexpr int OFF_XT   = OFF_RHS + Nn;
constexpr int OFF_SNAP = OFF_XT + Nn;         // 256 floats: GJ row/col snapshots
constexpr int SMEM_FLOATS = OFF_SNAP + 256;
static_assert(16 * PPART <= Mm * PA, "P1 partials must fit in dead A region");
static_assert(SMEM_FLOATS * 4 <= 227 * 1024, "");
}

extern __shared__ float smem[];

__global__ __launch_bounds__(NT, 1)
void osqp_admm_kernel(const float* __restrict__ gP,
                      const float* __restrict__ gq,
                      const float* __restrict__ gA,
                      const float* __restrict__ gl,
                      const float* __restrict__ gu,
                      float* __restrict__ gout)
{
    const int b   = blockIdx.x;
    const int tid = threadIdx.x;
    const int ty  = tid >> 4;        // 0..31
    const int tx  = tid & 15;        // 0..15
    const int wrp = tid >> 5;        // 0..15

    float* sA    = smem + OFF_A;
    float* sH    = smem + OFF_H;
    float* sq    = smem + OFF_Q;
    float* sl    = smem + OFF_L;
    float* su    = smem + OFF_U;
    float* sx    = smem + OFF_X;
    float* sz    = smem + OFF_Z;
    float* sy    = smem + OFF_Y;
    float* sw    = smem + OFF_W;
    float* srhs  = smem + OFF_RHS;
    float* sxt   = smem + OFF_XT;
    float* snap  = smem + OFF_SNAP;
    float* spart = smem + OFF_A;     // P1 partials (16 x PPART), aliases dead A

    // ------------------------------------------------------------------
    // Phase 0: load A (pitched), H = P + sigma*I, vectors; init state
    // ------------------------------------------------------------------
    {
        const float* pA = gA + (size_t)b * Mm * Nn;
        for (int idx = tid; idx < Mm * Nn; idx += NT)
            sA[(idx >> 7) * PA + (idx & 127)] = pA[idx];

        const float* pP = gP + (size_t)b * Nn * Nn;
        for (int idx = tid; idx < Nn * Nn; idx += NT) {
            int i = idx >> 7, j = idx & 127;
            float v = pP[idx];
            if (i == j) v += SIGMA;
            sH[i * PH + j] = v;
        }
        for (int n = tid; n < Nn; n += NT) { sq[n] = gq[(size_t)b * Nn + n]; sx[n] = 0.f; }
        for (int m = tid; m < Mm; m += NT) {
            sl[m] = gl[(size_t)b * Mm + m];
            su[m] = gu[(size_t)b * Mm + m];
            sz[m] = 0.f; sy[m] = 0.f; sw[m] = 0.f;
        }
    }
    __syncthreads();

    // ------------------------------------------------------------------
    // Phase 1: H += rho * A^T A   (8x4 register tile, 16x32 thread grid)
    // ------------------------------------------------------------------
    {
        const int ty1 = tid >> 5;    // 0..15
        const int tx1 = tid & 31;    // 0..31
        const int i0  = ty1 * 8;
        float acc[8][4];
        #pragma unroll
        for (int r = 0; r < 8; r++)
            #pragma unroll
            for (int c = 0; c < 4; c++) acc[r][c] = 0.f;

        #pragma unroll 2
        for (int m = 0; m < Mm; m++) {
            const float* row = sA + m * PA;
            float av[8], bv[4];
            #pragma unroll
            for (int r = 0; r < 8; r++) av[r] = row[i0 + r];       // broadcast
            #pragma unroll
            for (int c = 0; c < 4; c++) bv[c] = row[tx1 + 32 * c]; // coalesced
            #pragma unroll
            for (int r = 0; r < 8; r++)
                #pragma unroll
                for (int c = 0; c < 4; c++)
                    acc[r][c] += av[r] * bv[c];
        }
        #pragma unroll
        for (int r = 0; r < 8; r++)
            #pragma unroll
            for (int c = 0; c < 4; c++)
                sH[(i0 + r) * PH + tx1 + 32 * c] += RHO * acc[r][c];
    }
    __syncthreads();

    // ------------------------------------------------------------------
    // Phase 2: in-place Gauss-Jordan inverse of H (SPD -> no pivoting)
    // ------------------------------------------------------------------
    {
        float* srk = snap;         // row-k snapshot (128)
        float* sck = snap + Nn;    // col-k snapshot (128)
        for (int k = 0; k < Nn; k++) {
            const float p = 1.0f / sH[k * PH + k];
            if (tid < Nn)            srk[tid] = sH[k * PH + tid];
            else if (tid < 2 * Nn)   sck[tid - Nn] = sH[(tid - Nn) * PH + k];
            __syncthreads();

            const int  j   = tid & 127;
            const int  i0  = (tid >> 7) * 32;
            const float rs = srk[j] * p;
            const bool jk  = (j == k);
            #pragma unroll 4
            for (int i = i0; i < i0 + 32; i++) {
                float hij = sH[i * PH + j];
                float f   = sck[i];
                float nv;
                if (i == k) nv = jk ? p : rs;
                else        nv = jk ? (-f * p) : fmaf(-f, rs, hij);
                sH[i * PH + j] = nv;
            }
            __syncthreads();
        }
    }
    // sH now holds M1 = H^{-1}

    // ------------------------------------------------------------------
    // Phase 2b: load A and M1 into registers.
    //   rA[k][j] = A[ty+32k][tx+16j]   (6 x 8 per thread)
    //   rM[k][j] = M1[ty+32k][tx+16j]  (4 x 8 per thread)
    // ------------------------------------------------------------------
    float rA[6][8];
    #pragma unroll
    for (int k = 0; k < 6; k++)
        #pragma unroll
        for (int j = 0; j < 8; j++)
            rA[k][j] = sA[(ty + 32 * k) * PA + (tx + 16 * j)];

    float rM[4][8];
    #pragma unroll
    for (int k = 0; k < 4; k++)
        #pragma unroll
        for (int j = 0; j < 8; j++)
            rM[k][j] = sH[(ty + 32 * k) * PH + (tx + 16 * j)];

    __syncthreads();   // all sA reads done before spart aliases it

    // ------------------------------------------------------------------
    // Phase 3: 400 ADMM iterations; matrices in registers, 16 warps.
    // ------------------------------------------------------------------
    for (int it = 0; it < NITERS; it++) {
        // ---- P1: partial A^T w over this thread's 6 m-rows, then merge
        //      the warp's two ty-halves with one full-width shfl ----
        {
            float p[8];
            #pragma unroll
            for (int j = 0; j < 8; j++) p[j] = 0.f;
            #pragma unroll
            for (int k = 0; k < 6; k++) {
                const float wk = sw[ty + 32 * k];
                #pragma unroll
                for (int j = 0; j < 8; j++)
                    p[j] = fmaf(rA[k][j], wk, p[j]);
            }
            #pragma unroll
            for (int j = 0; j < 8; j++)
                p[j] += __shfl_xor_sync(0xffffffffu, p[j], 16);  // merge ty pair
            if (ty == 2 * wrp) {   // lower half stores the merged row
                #pragma unroll
                for (int j = 0; j < 8; j++)
                    spart[wrp * PPART + tx + 16 * j] = p[j];
            }
        }
        __syncthreads();

        // ---- P2: combine rhs (threads 0..127, one column; 16 partials) ----
        if (tid < Nn) {
            float s0 = 0.f, s1 = 0.f, s2 = 0.f, s3 = 0.f;
            #pragma unroll
            for (int t = 0; t < 16; t += 4) {
                s0 += spart[(t + 0) * PPART + tid];
                s1 += spart[(t + 1) * PPART + tid];
                s2 += spart[(t + 2) * PPART + tid];
                s3 += spart[(t + 3) * PPART + tid];
            }
            srhs[tid] = fmaf(SIGMA, sx[tid], ((s0 + s1) + (s2 + s3)) - sq[tid]);
        }
        __syncthreads();

        // ---- P3: xt = M1 * rhs (16-wide butterfly) + x update ----
        {
            float t0 = 0.f, t1 = 0.f, t2 = 0.f, t3 = 0.f;
            #pragma unroll
            for (int j = 0; j < 8; j++) {
                const float rj = srhs[tx + 16 * j];
                t0 = fmaf(rM[0][j], rj, t0);
                t1 = fmaf(rM[1][j], rj, t1);
                t2 = fmaf(rM[2][j], rj, t2);
                t3 = fmaf(rM[3][j], rj, t3);
            }
            #pragma unroll
            for (int s = 8; s >= 1; s >>= 1) {
                t0 += __shfl_xor_sync(0xffffffffu, t0, s, 16);
                t1 += __shfl_xor_sync(0xffffffffu, t1, s, 16);
                t2 += __shfl_xor_sync(0xffffffffu, t2, s, 16);
                t3 += __shfl_xor_sync(0xffffffffu, t3, s, 16);
            }
            // every lane holds all 4 sums; lanes 0..3 each write one element.
            // Explicit select chain (NOT dynamic indexing -> no local-mem spill).
            if (tx < 4) {
                float v = t0;
                if (tx == 1) v = t1;
                if (tx == 2) v = t2;
                if (tx == 3) v = t3;
                const int i = ty + 32 * tx;
                sxt[i] = v;
                sx[i]  = fmaf(ALPHA, v, (1.0f - ALPHA) * sx[i]);
            }
        }
        __syncthreads();

        // ---- P5: zt = A*xt (butterfly) fused with z/y/w update ----
        {
            float p0 = 0.f, p1 = 0.f, p2 = 0.f, p3 = 0.f, p4 = 0.f, p5 = 0.f;
            #pragma unroll
            for (int j = 0; j < 8; j++) {
                const float xj = sxt[tx + 16 * j];
                p0 = fmaf(rA[0][j], xj, p0);
                p1 = fmaf(rA[1][j], xj, p1);
                p2 = fmaf(rA[2][j], xj, p2);
                p3 = fmaf(rA[3][j], xj, p3);
                p4 = fmaf(rA[4][j], xj, p4);
                p5 = fmaf(rA[5][j], xj, p5);
            }
            #pragma unroll
            for (int s = 8; s >= 1; s >>= 1) {
                p0 += __shfl_xor_sync(0xffffffffu, p0, s, 16);
                p1 += __shfl_xor_sync(0xffffffffu, p1, s, 16);
                p2 += __shfl_xor_sync(0xffffffffu, p2, s, 16);
                p3 += __shfl_xor_sync(0xffffffffu, p3, s, 16);
                p4 += __shfl_xor_sync(0xffffffffu, p4, s, 16);
                p5 += __shfl_xor_sync(0xffffffffu, p5, s, 16);
            }
            // lanes 0..5 each update one m; explicit select chain (no spill)
            if (tx < 6) {
                float zt = p0;
                if (tx == 1) zt = p1;
                if (tx == 2) zt = p2;
                if (tx == 3) zt = p3;
                if (tx == 4) zt = p4;
                if (tx == 5) zt = p5;
                const int   m  = ty + 32 * tx;
                const float zc = fmaf(ALPHA, zt, (1.0f - ALPHA) * sz[m]);
                const float yv = sy[m];
                const float v  = fmaf(yv, 1.0f / RHO, zc);
                const float zn = fminf(fmaxf(v, sl[m]), su[m]);
                const float yn = fmaf(RHO, zc - zn, yv);
                sz[m] = zn;
                sy[m] = yn;
                sw[m] = fmaf(RHO, zn, -yn);
            }
        }
        __syncthreads();
    }

    // ------------------------------------------------------------------
    // Output
    // ------------------------------------------------------------------
    for (int n = tid; n < Nn; n += NT)
        gout[(size_t)b * Nn + n] = sx[n];
}

extern "C" void kernel_launch(void* const* d_in, const int* in_sizes, int n_in,
                              void* d_out, int out_size)
{
    const float* P = (const float*)d_in[0];   // (256,128,128)
    const float* q = (const float*)d_in[1];   // (256,128)
    const float* A = (const float*)d_in[2];   // (256,192,128)
    const float* l = (const float*)d_in[3];   // (256,192)
    const float* u = (const float*)d_in[4];   // (256,192)
    float* out = (float*)d_out;               // (256,128)

    const int smem_bytes = SMEM_FLOATS * (int)sizeof(float);
    // Unconditional (no static guard). Not stream-ordered -> capture-legal; idempotent.
    cudaFuncSetAttribute(osqp_admm_kernel,
                         cudaFuncAttributeMaxDynamicSharedMemorySize,
                         smem_bytes);
    osqp_admm_kernel<<<Bb, NT, smem_bytes>>>(P, q, A, l, u, out);
}

// round 12
// speedup vs baseline: 2.6133x; 1.4499x over previous
#include <cuda_runtime.h>

namespace {
constexpr int   Bb     = 256;
constexpr int   Nn     = 128;
constexpr int   Mm     = 192;
constexpr int   PA     = 129;   // A pitch (odd -> conflict-free rows AND columns)
constexpr int   PH     = 129;   // H/M1 pitch
constexpr int   PT     = 33;    // T-panel pitch
constexpr float RHO    = 0.1f;
constexpr float SIGMA  = 1e-6f;
constexpr float ALPHA  = 1.6f;
constexpr int   NITERS = 400;
constexpr int   NT     = 512;   // 16 warps

// shared memory layout (floats)
constexpr int OFF_A  = 0;                 // 192*129
constexpr int OFF_H  = OFF_A + Mm * PA;   // 128*129 (H then M1=H^-1)
constexpr int OFF_TP = OFF_H + Nn * PH;   // 128*33 T-panel; also GJ snapshots
constexpr int OFF_Q  = OFF_TP + Nn * PT;
constexpr int OFF_L  = OFF_Q + Nn;
constexpr int OFF_UB = OFF_L + Mm;
constexpr int OFF_C  = OFF_UB + Mm;
constexpr int OFF_W0 = OFF_C + Mm;        // w double buffer
constexpr int OFF_W1 = OFF_W0 + Mm;
constexpr int OFF_V  = OFF_W1 + Mm;
constexpr int OFF_G  = OFF_V + Mm;        // epilogue g (128)
constexpr int OFF_HV = OFF_G + Nn;        // h = M1*q (128)
constexpr int SMEM_FLOATS = OFF_HV + Nn;
static_assert(SMEM_FLOATS * 4 <= 227 * 1024, "");
}

extern __shared__ float smem[];

__global__ __launch_bounds__(NT, 1)
void osqp_admm_kernel(const float* __restrict__ gP,
                      const float* __restrict__ gq,
                      const float* __restrict__ gA,
                      const float* __restrict__ gl,
                      const float* __restrict__ gu,
                      float* __restrict__ gout)
{
    const int b   = blockIdx.x;
    const int tid = threadIdx.x;
    const int ty  = tid >> 4;        // 0..31
    const int tx  = tid & 15;        // 0..15

    float* sA  = smem + OFF_A;
    float* sH  = smem + OFF_H;
    float* sTp = smem + OFF_TP;
    float* sq  = smem + OFF_Q;
    float* sl  = smem + OFF_L;
    float* sub = smem + OFF_UB;
    float* sc  = smem + OFF_C;
    float* swb = smem + OFF_W0;      // [2][192]
    float* sv  = smem + OFF_V;
    float* sg  = smem + OFF_G;
    float* sh  = smem + OFF_HV;

    // ------------------------------------------------------------------
    // Phase 0: load A (pitched), H = P + sigma*I, vectors
    // ------------------------------------------------------------------
    {
        const float* pA = gA + (size_t)b * Mm * Nn;
        for (int idx = tid; idx < Mm * Nn; idx += NT)
            sA[(idx >> 7) * PA + (idx & 127)] = pA[idx];

        const float* pP = gP + (size_t)b * Nn * Nn;
        for (int idx = tid; idx < Nn * Nn; idx += NT) {
            int i = idx >> 7, j = idx & 127;
            float v = pP[idx];
            if (i == j) v += SIGMA;
            sH[i * PH + j] = v;
        }
        for (int n = tid; n < Nn; n += NT) sq[n] = gq[(size_t)b * Nn + n];
        for (int m = tid; m < Mm; m += NT) {
            sl[m]  = gl[(size_t)b * Mm + m];
            sub[m] = gu[(size_t)b * Mm + m];
            swb[m] = 0.f;            // w_0 = 0 (buffer 0)
        }
    }
    __syncthreads();

    // ------------------------------------------------------------------
    // Phase 1: H += rho * A^T A   (8x4 register tile, 16x32 thread grid)
    // ------------------------------------------------------------------
    {
        const int ty1 = tid >> 5;    // 0..15
        const int tx1 = tid & 31;    // 0..31
        const int i0  = ty1 * 8;
        float acc[8][4];
        #pragma unroll
        for (int r = 0; r < 8; r++)
            #pragma unroll
            for (int c = 0; c < 4; c++) acc[r][c] = 0.f;

        #pragma unroll 2
        for (int m = 0; m < Mm; m++) {
            const float* row = sA + m * PA;
            float av[8], bv[4];
            #pragma unroll
            for (int r = 0; r < 8; r++) av[r] = row[i0 + r];
            #pragma unroll
            for (int c = 0; c < 4; c++) bv[c] = row[tx1 + 32 * c];
            #pragma unroll
            for (int r = 0; r < 8; r++)
                #pragma unroll
                for (int c = 0; c < 4; c++)
                    acc[r][c] += av[r] * bv[c];
        }
        #pragma unroll
        for (int r = 0; r < 8; r++)
            #pragma unroll
            for (int c = 0; c < 4; c++)
                sH[(i0 + r) * PH + tx1 + 32 * c] += RHO * acc[r][c];
    }
    __syncthreads();

    // ------------------------------------------------------------------
    // Phase 2: in-place Gauss-Jordan inverse of H (SPD -> no pivoting)
    // snapshots live in the (not yet used) T-panel region.
    // ------------------------------------------------------------------
    {
        float* srk = sTp;          // row-k snapshot (128)
        float* sck = sTp + Nn;     // col-k snapshot (128)
        for (int k = 0; k < Nn; k++) {
            const float p = 1.0f / sH[k * PH + k];
            if (tid < Nn)            srk[tid] = sH[k * PH + tid];
            else if (tid < 2 * Nn)   sck[tid - Nn] = sH[(tid - Nn) * PH + k];
            __syncthreads();

            const int  j   = tid & 127;
            const int  i0  = (tid >> 7) * 32;
            const float rs = srk[j] * p;
            const bool jk  = (j == k);
            #pragma unroll 4
            for (int i = i0; i < i0 + 32; i++) {
                float hij = sH[i * PH + j];
                float f   = sck[i];
                float nv;
                if (i == k) nv = jk ? p : rs;
                else        nv = jk ? (-f * p) : fmaf(-f, rs, hij);
                sH[i * PH + j] = nv;
            }
            __syncthreads();
        }
    }
    // sH = M1 = H^{-1} (symmetric)

    // ------------------------------------------------------------------
    // Phase 3: h = M1*q ; c = -A*h
    // ------------------------------------------------------------------
    if (tid < Nn) {
        float a0 = 0.f, a1 = 0.f;
        const float* hp = sH + tid * PH;
        #pragma unroll 4
        for (int j = 0; j < Nn; j += 2) {
            a0 = fmaf(hp[j],     sq[j],     a0);
            a1 = fmaf(hp[j + 1], sq[j + 1], a1);
        }
        sh[tid] = a0 + a1;
    }
    __syncthreads();
    if (tid < Mm) {
        float a0 = 0.f, a1 = 0.f;
        const float* ap = sA + tid * PA;
        #pragma unroll 4
        for (int n = 0; n < Nn; n += 2) {
            a0 = fmaf(ap[n],     sh[n],     a0);
            a1 = fmaf(ap[n + 1], sh[n + 1], a1);
        }
        sc[tid] = -(a0 + a1);
    }
    __syncthreads();

    // ------------------------------------------------------------------
    // Phase 4: build S = A * M1 * A^T into registers rS[6][12]:
    //   rS[k][J] = S[ty+32k][tx+16J]
    // 6 panels of 32 columns; per panel:
    //   (a) Tp[i][c] = sum_j M1[i][j] * A[32p+c][j]   (i<128, c<32)
    //   (b) rS[k][2p+d] += sum_i A[ty+32k][i] * Tp[i][tx+16d]
    // Panel loop fully unrolled -> all rS indices compile-time (no spill).
    // ------------------------------------------------------------------
    float rS[6][12];
    #pragma unroll
    for (int k = 0; k < 6; k++)
        #pragma unroll
        for (int J = 0; J < 12; J++) rS[k][J] = 0.f;

    {
        const int ty3 = tid >> 4;    // 0..31 (rows i = ty3 + 32r)
        const int tx3 = tid & 15;    // cols c = tx3 + 16d
        #pragma unroll
        for (int p = 0; p < 6; p++) {
            // ---- (a) T panel ----
            float ta[4][2];
            #pragma unroll
            for (int r = 0; r < 4; r++) { ta[r][0] = 0.f; ta[r][1] = 0.f; }
            #pragma unroll 2
            for (int j = 0; j < Nn; j++) {
                float mv[4], av[2];
                #pragma unroll
                for (int r = 0; r < 4; r++) mv[r] = sH[(ty3 + 32 * r) * PH + j];
                #pragma unroll
                for (int d = 0; d < 2; d++) av[d] = sA[(32 * p + tx3 + 16 * d) * PA + j];
                #pragma unroll
                for (int r = 0; r < 4; r++) {
                    ta[r][0] = fmaf(mv[r], av[0], ta[r][0]);
                    ta[r][1] = fmaf(mv[r], av[1], ta[r][1]);
                }
            }
            #pragma unroll
            for (int r = 0; r < 4; r++) {
                sTp[(ty3 + 32 * r) * PT + tx3]      = ta[r][0];
                sTp[(ty3 + 32 * r) * PT + tx3 + 16] = ta[r][1];
            }
            __syncthreads();

            // ---- (b) accumulate into rS columns 2p, 2p+1 ----
            #pragma unroll 2
            for (int i = 0; i < Nn; i++) {
                float uv[6], tv0, tv1;
                #pragma unroll
                for (int k = 0; k < 6; k++) uv[k] = sA[(ty + 32 * k) * PA + i];
                tv0 = sTp[i * PT + tx];
                tv1 = sTp[i * PT + tx + 16];
                #pragma unroll
                for (int k = 0; k < 6; k++) {
                    rS[k][2 * p]     = fmaf(uv[k], tv0, rS[k][2 * p]);
                    rS[k][2 * p + 1] = fmaf(uv[k], tv1, rS[k][2 * p + 1]);
                }
            }
            __syncthreads();
        }
    }

    // ------------------------------------------------------------------
    // Phase 5: owner-register state init (thread (ty,tx<6) owns m=ty+32tx)
    // ------------------------------------------------------------------
    const int  mown = ty + 32 * tx;
    float rz = 0.f, ry = 0.f, ru = 0.f, rw = 0.f;
    float rl = 0.f, rub = 0.f, rc = 0.f;
    if (tx < 6) { rl = sl[mown]; rub = sub[mown]; rc = sc[mown]; }
    __syncthreads();

    // ------------------------------------------------------------------
    // Phase 6: 400 iterations, ONE matvec + ONE barrier each.
    //   zt = S*w + c ; zc = a*zt+(1-a)z ; z=clip(zc+y/rho) ; y+=rho(zc-z)
    //   v <- (1-a)v + a*w_t  (x-recursion collapsed) ; w' = rho*z - y
    // ------------------------------------------------------------------
    for (int it = 0; it < NITERS; it++) {
        const float* wb = swb + (it & 1) * Mm;
        float a0 = 0.f, a1 = 0.f, a2 = 0.f, a3 = 0.f, a4 = 0.f, a5 = 0.f;
        #pragma unroll
        for (int J = 0; J < 12; J++) {
            const float wj = wb[tx + 16 * J];
            a0 = fmaf(rS[0][J], wj, a0);
            a1 = fmaf(rS[1][J], wj, a1);
            a2 = fmaf(rS[2][J], wj, a2);
            a3 = fmaf(rS[3][J], wj, a3);
            a4 = fmaf(rS[4][J], wj, a4);
            a5 = fmaf(rS[5][J], wj, a5);
        }
        #pragma unroll
        for (int s = 8; s >= 1; s >>= 1) {
            a0 += __shfl_xor_sync(0xffffffffu, a0, s, 16);
            a1 += __shfl_xor_sync(0xffffffffu, a1, s, 16);
            a2 += __shfl_xor_sync(0xffffffffu, a2, s, 16);
            a3 += __shfl_xor_sync(0xffffffffu, a3, s, 16);
            a4 += __shfl_xor_sync(0xffffffffu, a4, s, 16);
            a5 += __shfl_xor_sync(0xffffffffu, a5, s, 16);
        }
        if (tx < 6) {
            float zt = a0;                    // explicit select (no dyn index)
            if (tx == 1) zt = a1;
            if (tx == 2) zt = a2;
            if (tx == 3) zt = a3;
            if (tx == 4) zt = a4;
            if (tx == 5) zt = a5;
            zt += rc;
            ru = fmaf(1.0f - ALPHA, ru, ALPHA * rw);       // v-recursion (w_t)
            const float zc = fmaf(ALPHA, zt, (1.0f - ALPHA) * rz);
            const float vv = fmaf(ry, 1.0f / RHO, zc);
            const float zn = fminf(fmaxf(vv, rl), rub);
            ry = fmaf(RHO, zc - zn, ry);
            rz = zn;
            rw = fmaf(RHO, zn, -ry);
            swb[((it + 1) & 1) * Mm + mown] = rw;
        }
        __syncthreads();
    }

    // ------------------------------------------------------------------
    // Phase 7: epilogue  x = M1*(A^T v - q)
    // ------------------------------------------------------------------
    if (tx < 6) sv[mown] = ru;
    __syncthreads();
    if (tid < Nn) {
        float a0 = 0.f, a1 = 0.f;
        #pragma unroll 4
        for (int m = 0; m < Mm; m += 2) {
            a0 = fmaf(sA[m * PA + tid],       sv[m],     a0);
            a1 = fmaf(sA[(m + 1) * PA + tid], sv[m + 1], a1);
        }
        sg[tid] = (a0 + a1) - sq[tid];
    }
    __syncthreads();
    if (tid < Nn) {
        float a0 = 0.f, a1 = 0.f;
        const float* hp = sH + tid * PH;
        #pragma unroll 4
        for (int j = 0; j < Nn; j += 2) {
            a0 = fmaf(hp[j],     sg[j],     a0);
            a1 = fmaf(hp[j + 1], sg[j + 1], a1);
        }
        gout[(size_t)b * Nn + tid] = a0 + a1;
    }
}

extern "C" void kernel_launch(void* const* d_in, const int* in_sizes, int n_in,
                              void* d_out, int out_size)
{
    const float* P = (const float*)d_in[0];   // (256,128,128)
    const float* q = (const float*)d_in[1];   // (256,128)
    const float* A = (const float*)d_in[2];   // (256,192,128)
    const float* l = (const float*)d_in[3];   // (256,192)
    const float* u = (const float*)d_in[4];   // (256,192)
    float* out = (float*)d_out;               // (256,128)

    const int smem_bytes = SMEM_FLOATS * (int)sizeof(float);
    // Unconditional (no static guard). Not stream-ordered -> capture-legal; idempotent.
    cudaFuncSetAttribute(osqp_admm_kernel,
                         cudaFuncAttributeMaxDynamicSharedMemorySize,
                         smem_bytes);
    osqp_admm_kernel<<<Bb, NT, smem_bytes>>>(P, q, A, l, u, out);
}

// round 13
// speedup vs baseline: 2.8162x; 1.0776x over previous
#include <cuda_runtime.h>
#include <cstring>

namespace {
constexpr int   Bb     = 256;
constexpr int   Nn     = 128;
constexpr int   Mm     = 192;
constexpr int   PA     = 132;   // pitch: mult of 4 -> every row 16B aligned
constexpr int   PH     = 132;
constexpr int   PTT    = 132;   // TpT pitch (TpT[c][i], c<64, i<128)
constexpr float RHO    = 0.1f;
constexpr float SIGMA  = 1e-6f;
constexpr float ALPHA  = 1.6f;
constexpr int   NITERS = 400;
constexpr int   NT     = 512;

// shared memory layout (floats); offsets all mult of 4 (16B aligned)
constexpr int OFF_A   = 0;                  // 192*132 = 25344
constexpr int OFF_H   = OFF_A + Mm * PA;    // 128*132 = 16896
constexpr int OFF_TPT = OFF_H + Nn * PH;    // 64*132  = 8448 (also GJ snapshots)
constexpr int OFF_Q   = OFF_TPT + 64 * PTT;
constexpr int OFF_L   = OFF_Q + Nn;
constexpr int OFF_UB  = OFF_L + Mm;
constexpr int OFF_C   = OFF_UB + Mm;
constexpr int OFF_WT0 = OFF_C + Mm;         // transposed w double buffer: [16][12]
constexpr int OFF_WT1 = OFF_WT0 + 192;
constexpr int OFF_V   = OFF_WT1 + 192;
constexpr int OFF_G   = OFF_V + Mm;
constexpr int OFF_HV  = OFF_G + Nn;
constexpr int SMEM_FLOATS = OFF_HV + Nn;    // 52224 floats = 208896 B
static_assert(SMEM_FLOATS * 4 <= 227 * 1024, "");
}

typedef unsigned long long u64;

__device__ __forceinline__ u64 fma2(u64 a, u64 b, u64 c) {
    u64 d;
    asm("fma.rn.f32x2 %0, %1, %2, %3;" : "=l"(d) : "l"(a), "l"(b), "l"(c));
    return d;
}
__device__ __forceinline__ u64 splat2(float v) {
    u64 d; unsigned u = __float_as_uint(v);
    asm("mov.b64 %0, {%1, %1};" : "=l"(d) : "r"(u));
    return d;
}
__device__ __forceinline__ float hadd2(u64 p) {
    float2 f; memcpy(&f, &p, 8); return f.x + f.y;
}
__device__ __forceinline__ u64 pack2(float a, float b) {
    float2 f; f.x = a; f.y = b; u64 u; memcpy(&u, &f, 8); return u;
}
__device__ __forceinline__ void unpack2(u64 p, float& a, float& b) {
    float2 f; memcpy(&f, &p, 8); a = f.x; b = f.y;
}

extern __shared__ float smem[];

__global__ __launch_bounds__(NT, 1)
void osqp_admm_kernel(const float* __restrict__ gP,
                      const float* __restrict__ gq,
                      const float* __restrict__ gA,
                      const float* __restrict__ gl,
                      const float* __restrict__ gu,
                      float* __restrict__ gout)
{
    const int b   = blockIdx.x;
    const int tid = threadIdx.x;
    const int ty  = tid >> 4;        // 0..31
    const int tx  = tid & 15;        // 0..15

    float* sA   = smem + OFF_A;
    float* sH   = smem + OFF_H;
    float* sTpT = smem + OFF_TPT;
    float* sq   = smem + OFF_Q;
    float* sl   = smem + OFF_L;
    float* sub  = smem + OFF_UB;
    float* sc   = smem + OFF_C;
    float* swt  = smem + OFF_WT0;    // [2][192] transposed w
    float* sv   = smem + OFF_V;
    float* sg   = smem + OFF_G;
    float* sh   = smem + OFF_HV;

    // ------------------------------------------------------------------
    // Phase 0: load A (pitched), H = P + sigma*I, vectors; wT0 = 0
    // ------------------------------------------------------------------
    {
        const float* pA = gA + (size_t)b * Mm * Nn;
        for (int idx = tid; idx < Mm * Nn; idx += NT)
            sA[(idx >> 7) * PA + (idx & 127)] = pA[idx];

        const float* pP = gP + (size_t)b * Nn * Nn;
        for (int idx = tid; idx < Nn * Nn; idx += NT) {
            int i = idx >> 7, j = idx & 127;
            float v = pP[idx];
            if (i == j) v += SIGMA;
            sH[i * PH + j] = v;
        }
        for (int n = tid; n < Nn; n += NT) sq[n] = gq[(size_t)b * Nn + n];
        for (int m = tid; m < Mm; m += NT) {
            sl[m]  = gl[(size_t)b * Mm + m];
            sub[m] = gu[(size_t)b * Mm + m];
            swt[m] = 0.f;            // buffer 0
        }
    }
    __syncthreads();

    // ------------------------------------------------------------------
    // Phase 1: H += rho * A^T A   — packed over output-row pairs.
    // thread (ty1,tx1): rows i0..i0+7 (4 packed pairs), cols tx1+32c.
    // ------------------------------------------------------------------
    {
        const int ty1 = tid >> 5;    // 0..15
        const int tx1 = tid & 31;    // 0..31
        const int i0  = ty1 * 8;
        u64 acc[4][4];
        #pragma unroll
        for (int r = 0; r < 4; r++)
            #pragma unroll
            for (int c = 0; c < 4; c++) acc[r][c] = 0ull;

        #pragma unroll 2
        for (int m = 0; m < Mm; m++) {
            const float* row = sA + m * PA;
            const u64* ap = reinterpret_cast<const u64*>(row + i0);  // 16B aligned
            u64 p0 = ap[0], p1 = ap[1], p2 = ap[2], p3 = ap[3];
            u64 bs[4];
            #pragma unroll
            for (int c = 0; c < 4; c++) bs[c] = splat2(row[tx1 + 32 * c]);
            #pragma unroll
            for (int c = 0; c < 4; c++) {
                acc[0][c] = fma2(p0, bs[c], acc[0][c]);
                acc[1][c] = fma2(p1, bs[c], acc[1][c]);
                acc[2][c] = fma2(p2, bs[c], acc[2][c]);
                acc[3][c] = fma2(p3, bs[c], acc[3][c]);
            }
        }
        #pragma unroll
        for (int r = 0; r < 4; r++)
            #pragma unroll
            for (int c = 0; c < 4; c++) {
                float lo, hi; unpack2(acc[r][c], lo, hi);
                sH[(i0 + 2 * r)     * PH + tx1 + 32 * c] += RHO * lo;
                sH[(i0 + 2 * r + 1) * PH + tx1 + 32 * c] += RHO * hi;
            }
    }
    __syncthreads();

    // ------------------------------------------------------------------
    // Phase 2: in-place Gauss-Jordan inverse of H (SPD -> no pivoting)
    // snapshots in the (unused yet) TpT region.
    // ------------------------------------------------------------------
    {
        float* srk = sTpT;
        float* sck = sTpT + Nn;
        for (int k = 0; k < Nn; k++) {
            const float p = 1.0f / sH[k * PH + k];
            if (tid < Nn)            srk[tid] = sH[k * PH + tid];
            else if (tid < 2 * Nn)   sck[tid - Nn] = sH[(tid - Nn) * PH + k];
            __syncthreads();

            const int  j   = tid & 127;
            const int  i0  = (tid >> 7) * 32;
            const float rs = srk[j] * p;
            const bool jk  = (j == k);
            #pragma unroll 4
            for (int i = i0; i < i0 + 32; i++) {
                float hij = sH[i * PH + j];
                float f   = sck[i];
                float nv;
                if (i == k) nv = jk ? p : rs;
                else        nv = jk ? (-f * p) : fmaf(-f, rs, hij);
                sH[i * PH + j] = nv;
            }
            __syncthreads();
        }
    }
    // sH = M1 = H^{-1}

    // ------------------------------------------------------------------
    // Phase 3: h = M1*q ; c = -A*h
    // ------------------------------------------------------------------
    if (tid < Nn) {
        float a0 = 0.f, a1 = 0.f;
        const float* hp = sH + tid * PH;
        #pragma unroll 4
        for (int j = 0; j < Nn; j += 2) {
            a0 = fmaf(hp[j],     sq[j],     a0);
            a1 = fmaf(hp[j + 1], sq[j + 1], a1);
        }
        sh[tid] = a0 + a1;
    }
    __syncthreads();
    if (tid < Mm) {
        float a0 = 0.f, a1 = 0.f;
        const float* ap = sA + tid * PA;
        #pragma unroll 4
        for (int n = 0; n < Nn; n += 2) {
            a0 = fmaf(ap[n],     sh[n],     a0);
            a1 = fmaf(ap[n + 1], sh[n + 1], a1);
        }
        sc[tid] = -(a0 + a1);
    }
    __syncthreads();

    // ------------------------------------------------------------------
    // Phase 4: S = A*M1*A^T into packed registers rSp[6][6]:
    //   rSp[k][t] = pack(S[ty+32k][tx+32t], S[ty+32k][tx+32t+16])
    // 3 panels of 64 columns. Per panel p:
    //  (a) TpT[c][i] = sum_j M1[i][j]*A[64p+c][j]   (packed over j)
    //  (b) S[row][64p+cl] = sum_i A[row][i]*TpT[cl][i] (packed over i)
    // ------------------------------------------------------------------
    u64 rSp[6][6];
    {
        const int ty3 = tid >> 4;    // 0..31: rows i = ty3+32r
        const int tx3 = tid & 15;    // cols c = tx3+16d
        #pragma unroll
        for (int p = 0; p < 3; p++) {
            // ---- (a) ----
            u64 ta[4][4];
            #pragma unroll
            for (int r = 0; r < 4; r++)
                #pragma unroll
                for (int d = 0; d < 4; d++) ta[r][d] = 0ull;
            #pragma unroll 2
            for (int j = 0; j < Nn; j += 2) {
                u64 mp[4], an[4];
                #pragma unroll
                for (int r = 0; r < 4; r++)
                    mp[r] = *reinterpret_cast<const u64*>(sH + (ty3 + 32 * r) * PH + j);
                #pragma unroll
                for (int d = 0; d < 4; d++)
                    an[d] = *reinterpret_cast<const u64*>(sA + (64 * p + tx3 + 16 * d) * PA + j);
                #pragma unroll
                for (int r = 0; r < 4; r++)
                    #pragma unroll
                    for (int d = 0; d < 4; d++)
                        ta[r][d] = fma2(mp[r], an[d], ta[r][d]);
            }
            #pragma unroll
            for (int r = 0; r < 4; r++)
                #pragma unroll
                for (int d = 0; d < 4; d++)
                    sTpT[(tx3 + 16 * d) * PTT + (ty3 + 32 * r)] = hadd2(ta[r][d]);
            __syncthreads();

            // ---- (b) ----
            u64 bacc[6][4];
            #pragma unroll
            for (int k = 0; k < 6; k++)
                #pragma unroll
                for (int d = 0; d < 4; d++) bacc[k][d] = 0ull;
            #pragma unroll 2
            for (int i = 0; i < Nn; i += 2) {
                u64 apk[6], tpd[4];
                #pragma unroll
                for (int k = 0; k < 6; k++)
                    apk[k] = *reinterpret_cast<const u64*>(sA + (ty + 32 * k) * PA + i);
                #pragma unroll
                for (int d = 0; d < 4; d++)
                    tpd[d] = *reinterpret_cast<const u64*>(sTpT + (tx + 16 * d) * PTT + i);
                #pragma unroll
                for (int k = 0; k < 6; k++)
                    #pragma unroll
                    for (int d = 0; d < 4; d++)
                        bacc[k][d] = fma2(apk[k], tpd[d], bacc[k][d]);
            }
            #pragma unroll
            for (int k = 0; k < 6; k++) {
                rSp[k][2 * p]     = pack2(hadd2(bacc[k][0]), hadd2(bacc[k][1]));
                rSp[k][2 * p + 1] = pack2(hadd2(bacc[k][2]), hadd2(bacc[k][3]));
            }
            __syncthreads();
        }
    }

    // ------------------------------------------------------------------
    // Phase 5: owner-register state (thread (ty,tx<6) owns m = ty+32tx)
    // ------------------------------------------------------------------
    const int  mown = ty + 32 * tx;
    float rz = 0.f, ry = 0.f, ru = 0.f, rw = 0.f;
    float rl = 0.f, rub = 0.f, rc = 0.f;
    if (tx < 6) { rl = sl[mown]; rub = sub[mown]; rc = sc[mown]; }
    __syncthreads();

    // ------------------------------------------------------------------
    // Phase 6: 400 iterations, one packed matvec + one barrier each.
    // wT layout: wT[t][J] = w[t + 16J] at swt[buf*192 + t*12 + J].
    // ------------------------------------------------------------------
    for (int it = 0; it < NITERS; it++) {
        const float* wb = swt + (it & 1) * 192 + tx * 12;
        const ulonglong2* wq = reinterpret_cast<const ulonglong2*>(wb);
        ulonglong2 q0 = wq[0], q1 = wq[1], q2 = wq[2];
        u64 a0 = 0ull, a1 = 0ull, a2 = 0ull, a3 = 0ull, a4 = 0ull, a5 = 0ull;
        a0 = fma2(rSp[0][0], q0.x, a0); a1 = fma2(rSp[1][0], q0.x, a1);
        a2 = fma2(rSp[2][0], q0.x, a2); a3 = fma2(rSp[3][0], q0.x, a3);
        a4 = fma2(rSp[4][0], q0.x, a4); a5 = fma2(rSp[5][0], q0.x, a5);
        a0 = fma2(rSp[0][1], q0.y, a0); a1 = fma2(rSp[1][1], q0.y, a1);
        a2 = fma2(rSp[2][1], q0.y, a2); a3 = fma2(rSp[3][1], q0.y, a3);
        a4 = fma2(rSp[4][1], q0.y, a4); a5 = fma2(rSp[5][1], q0.y, a5);
        a0 = fma2(rSp[0][2], q1.x, a0); a1 = fma2(rSp[1][2], q1.x, a1);
        a2 = fma2(rSp[2][2], q1.x, a2); a3 = fma2(rSp[3][2], q1.x, a3);
        a4 = fma2(rSp[4][2], q1.x, a4); a5 = fma2(rSp[5][2], q1.x, a5);
        a0 = fma2(rSp[0][3], q1.y, a0); a1 = fma2(rSp[1][3], q1.y, a1);
        a2 = fma2(rSp[2][3], q1.y, a2); a3 = fma2(rSp[3][3], q1.y, a3);
        a4 = fma2(rSp[4][3], q1.y, a4); a5 = fma2(rSp[5][3], q1.y, a5);
        a0 = fma2(rSp[0][4], q2.x, a0); a1 = fma2(rSp[1][4], q2.x, a1);
        a2 = fma2(rSp[2][4], q2.x, a2); a3 = fma2(rSp[3][4], q2.x, a3);
        a4 = fma2(rSp[4][4], q2.x, a4); a5 = fma2(rSp[5][4], q2.x, a5);
        a0 = fma2(rSp[0][5], q2.y, a0); a1 = fma2(rSp[1][5], q2.y, a1);
        a2 = fma2(rSp[2][5], q2.y, a2); a3 = fma2(rSp[3][5], q2.y, a3);
        a4 = fma2(rSp[4][5], q2.y, a4); a5 = fma2(rSp[5][5], q2.y, a5);

        float s0 = hadd2(a0), s1 = hadd2(a1), s2 = hadd2(a2),
              s3 = hadd2(a3), s4 = hadd2(a4), s5 = hadd2(a5);
        #pragma unroll
        for (int s = 8; s >= 1; s >>= 1) {
            s0 += __shfl_xor_sync(0xffffffffu, s0, s, 16);
            s1 += __shfl_xor_sync(0xffffffffu, s1, s, 16);
            s2 += __shfl_xor_sync(0xffffffffu, s2, s, 16);
            s3 += __shfl_xor_sync(0xffffffffu, s3, s, 16);
            s4 += __shfl_xor_sync(0xffffffffu, s4, s, 16);
            s5 += __shfl_xor_sync(0xffffffffu, s5, s, 16);
        }
        if (tx < 6) {
            float zt = s0;                    // explicit select (no dyn index)
            if (tx == 1) zt = s1;
            if (tx == 2) zt = s2;
            if (tx == 3) zt = s3;
            if (tx == 4) zt = s4;
            if (tx == 5) zt = s5;
            zt += rc;
            ru = fmaf(1.0f - ALPHA, ru, ALPHA * rw);       // v-recursion
            const float zc = fmaf(ALPHA, zt, (1.0f - ALPHA) * rz);
            const float vv = fmaf(ry, 1.0f / RHO, zc);
            const float zn = fminf(fmaxf(vv, rl), rub);
            ry = fmaf(RHO, zc - zn, ry);
            rz = zn;
            rw = fmaf(RHO, zn, -ry);
            swt[((it + 1) & 1) * 192 + (mown & 15) * 12 + (mown >> 4)] = rw;
        }
        __syncthreads();
    }

    // ------------------------------------------------------------------
    // Phase 7: epilogue  x = M1*(A^T v - q)
    // ------------------------------------------------------------------
    if (tx < 6) sv[mown] = ru;
    __syncthreads();
    if (tid < Nn) {
        float a0 = 0.f, a1 = 0.f;
        #pragma unroll 4
        for (int m = 0; m < Mm; m += 2) {
            a0 = fmaf(sA[m * PA + tid],       sv[m],     a0);
            a1 = fmaf(sA[(m + 1) * PA + tid], sv[m + 1], a1);
        }
        sg[tid] = (a0 + a1) - sq[tid];
    }
    __syncthreads();
    if (tid < Nn) {
        float a0 = 0.f, a1 = 0.f;
        const float* hp = sH + tid * PH;
        #pragma unroll 4
        for (int j = 0; j < Nn; j += 2) {
            a0 = fmaf(hp[j],     sg[j],     a0);
            a1 = fmaf(hp[j + 1], sg[j + 1], a1);
        }
        gout[(size_t)b * Nn + tid] = a0 + a1;
    }
}

extern "C" void kernel_launch(void* const* d_in, const int* in_sizes, int n_in,
                              void* d_out, int out_size)
{
    const float* P = (const float*)d_in[0];   // (256,128,128)
    const float* q = (const float*)d_in[1];   // (256,128)
    const float* A = (const float*)d_in[2];   // (256,192,128)
    const float* l = (const float*)d_in[3];   // (256,192)
    const float* u = (const float*)d_in[4];   // (256,192)
    float* out = (float*)d_out;               // (256,128)

    const int smem_bytes = SMEM_FLOATS * (int)sizeof(float);
    // Unconditional (no static guard). Not stream-ordered -> capture-legal; idempotent.
    cudaFuncSetAttribute(osqp_admm_kernel,
                         cudaFuncAttributeMaxDynamicSharedMemorySize,
                         smem_bytes);
    osqp_admm_kernel<<<Bb, NT, smem_bytes>>>(P, q, A, l, u, out);
}